// round 7
// baseline (speedup 1.0000x reference)
#include <cuda_runtime.h>

// out[b,v] = sum_c x[b,c,v] * (conv_w[c] + w_b*scale_b) + (conv_b + shift_b)
//   w_b     = silu(z[b]) . hwd_w + hwd_b
//   scale_b = silu(z[b]) . c_w[0] + c_b[0]
//   shift_b = silu(z[b]) . c_w[1] + c_b[1]
//
// B=8, C=16, 96^3 voxels. Pure HBM stream: 452 MB read + 28 MB write.
// Channel-major blocking: each block covers 512 consecutive float4s (8 KB)
// per channel, unroll-2 per thread, so each DRAM-side stream sees 4x longer
// contiguous bursts than the 1-float4-per-thread variant.

#define C_CH   16
#define NV4    221184LL        // 96*96*96 / 4
#define TPB    256
#define UNROLL 2               // float4s per thread; TPB*UNROLL = 512 per block
// NV4 / (TPB*UNROLL) = 221184 / 512 = 432 exactly

__global__ __launch_bounds__(TPB, 8)
void fused_zprjs_conv_kernel(const float* __restrict__ x,
                             const float* __restrict__ z_prjs,
                             const float* __restrict__ conv_w,
                             const float* __restrict__ conv_b,
                             const float* __restrict__ hwd_w,
                             const float* __restrict__ hwd_b,
                             const float* __restrict__ c_w,
                             const float* __restrict__ c_b,
                             float* __restrict__ out)
{
    __shared__ float s_coef[C_CH];
    __shared__ float s_bias;

    const int b = blockIdx.y;

    if (threadIdx.x == 0) {
        const float* z = z_prjs + b * 5;
        float z0 = z[0], z1 = z[1], z2 = z[2], z3 = z[3], z4 = z[4];
        float s0 = z0 / (1.f + __expf(-z0));
        float s1 = z1 / (1.f + __expf(-z1));
        float s2 = z2 / (1.f + __expf(-z2));
        float s3 = z3 / (1.f + __expf(-z3));
        float s4 = z4 / (1.f + __expf(-z4));
        float wv = hwd_b[0] + s0 * hwd_w[0] + s1 * hwd_w[1] + s2 * hwd_w[2]
                            + s3 * hwd_w[3] + s4 * hwd_w[4];
        float sc = c_b[0] + s0 * c_w[0] + s1 * c_w[1] + s2 * c_w[2]
                          + s3 * c_w[3] + s4 * c_w[4];
        float sh = c_b[1] + s0 * c_w[5] + s1 * c_w[6] + s2 * c_w[7]
                          + s3 * c_w[8] + s4 * c_w[9];
        float a = wv * sc;
        s_bias = conv_b[0] + sh;
        #pragma unroll
        for (int c = 0; c < C_CH; c++) s_coef[c] = conv_w[c] + a;
    }
    __syncthreads();

    // Block-owned range: [base, base + TPB*UNROLL) float4s of every channel.
    const long long base = (long long)blockIdx.x * (TPB * UNROLL) + threadIdx.x;

    const float4* __restrict__ xb =
        reinterpret_cast<const float4*>(x) + (long long)b * C_CH * NV4 + base;
    const float bias = s_bias;

    float4 acc0 = make_float4(bias, bias, bias, bias);
    float4 acc1 = acc0;

    #pragma unroll
    for (int c = 0; c < C_CH; c++) {
        const float4* p = xb + (long long)c * NV4;
        float4 xv0 = __ldg(p);
        float4 xv1 = __ldg(p + TPB);
        float w = s_coef[c];            // broadcast LDS, conflict-free
        acc0.x = fmaf(xv0.x, w, acc0.x);
        acc0.y = fmaf(xv0.y, w, acc0.y);
        acc0.z = fmaf(xv0.z, w, acc0.z);
        acc0.w = fmaf(xv0.w, w, acc0.w);
        acc1.x = fmaf(xv1.x, w, acc1.x);
        acc1.y = fmaf(xv1.y, w, acc1.y);
        acc1.z = fmaf(xv1.z, w, acc1.z);
        acc1.w = fmaf(xv1.w, w, acc1.w);
    }

    float4* __restrict__ ob = reinterpret_cast<float4*>(out) + (long long)b * NV4 + base;
    __stcs(ob, acc0);
    __stcs(ob + TPB, acc1);
}

extern "C" void kernel_launch(void* const* d_in, const int* in_sizes, int n_in,
                              void* d_out, int out_size)
{
    const float* x      = (const float*)d_in[0];
    const float* z_prjs = (const float*)d_in[1];
    const float* conv_w = (const float*)d_in[2];
    const float* conv_b = (const float*)d_in[3];
    const float* hwd_w  = (const float*)d_in[4];
    const float* hwd_b  = (const float*)d_in[5];
    const float* c_w    = (const float*)d_in[6];
    const float* c_b    = (const float*)d_in[7];
    float* out = (float*)d_out;

    dim3 grid((unsigned)(NV4 / (TPB * UNROLL)), 8, 1);   // 432 x 8 = 3456 blocks
    fused_zprjs_conv_kernel<<<grid, TPB>>>(x, z_prjs, conv_w, conv_b,
                                           hwd_w, hwd_b, c_w, c_b, out);
}